// round 14
// baseline (speedup 1.0000x reference)
#include <cuda_runtime.h>
#include <cuda_fp16.h>
#include <cstdint>

#define BATCH   128
#define IN_DIM  1024
#define OUT_DIM 1024
#define ZD      128

#define NO_     4                    // o-values per CTA (k_main)
#define ISPLIT  2                    // i-range splits
#define I_PER   (IN_DIM / ISPLIT)    // 512
#define ITERS   (I_PER / 8)         // 64
#define ROWW    80                   // smem row stride in words: 16 mod 32 -> LDS.128 conflict-free

// ---------------- helpers ----------------
__device__ __forceinline__ void mma_fp16(float* c, const uint32_t* a,
                                         uint32_t b0, uint32_t b1) {
    asm volatile(
        "mma.sync.aligned.m16n8k16.row.col.f32.f16.f16.f32 "
        "{%0,%1,%2,%3},{%4,%5,%6,%7},{%8,%9},{%0,%1,%2,%3};"
        : "+f"(c[0]), "+f"(c[1]), "+f"(c[2]), "+f"(c[3])
        : "r"(a[0]), "r"(a[1]), "r"(a[2]), "r"(a[3]), "r"(b0), "r"(b1));
}

__device__ __forceinline__ uint32_t f2h2(float lo, float hi) {
    __half2 h = __float22half2_rn(make_float2(lo, hi));
    return *(uint32_t*)&h;
}

// ---------------- k_pre: out = bb + dbb + z@dbW^T + x@(bw+dwb)^T (full overwrite) ----------------
__global__ void __launch_bounds__(256)
k_pre(const float* __restrict__ x, const float* __restrict__ z,
      const float* __restrict__ bw, const float* __restrict__ dwb,
      const float* __restrict__ bb, const float* __restrict__ dbW,
      const float* __restrict__ dbb, float* __restrict__ out) {
    __shared__ float as_[32][36];
    __shared__ float wsm[32][36];
    const int t  = threadIdx.x;
    const int o0 = blockIdx.x * 32;
    const int b0 = blockIdx.y * 32;
    const int ty = t >> 4;   // 0..15 -> 2 batch rows
    const int tx = t & 15;   // 0..15 -> 2 o cols
    const int lr = t >> 3;
    const int lc = (t & 7) * 4;
    float acc[2][2] = {};
    for (int kt = 0; kt < 36; kt++) {
        float4 av, wv;
        if (kt < 4) {
            av = *(const float4*)(z   + (size_t)(b0 + lr) * ZD + kt * 32 + lc);
            wv = *(const float4*)(dbW + (size_t)(o0 + lr) * ZD + kt * 32 + lc);
        } else {
            av = *(const float4*)(x + (size_t)(b0 + lr) * IN_DIM + (kt - 4) * 32 + lc);
            size_t off = (size_t)(o0 + lr) * IN_DIM + (kt - 4) * 32 + lc;
            float4 a = *(const float4*)(bw + off);
            float4 d = *(const float4*)(dwb + off);
            wv = make_float4(a.x + d.x, a.y + d.y, a.z + d.z, a.w + d.w);
        }
        __syncthreads();
        *(float4*)&as_[lr][lc] = av;
        *(float4*)&wsm[lr][lc] = wv;
        __syncthreads();
#pragma unroll 8
        for (int j = 0; j < 32; j++) {
            float a0 = as_[ty * 2][j],     a1 = as_[ty * 2 + 1][j];
            float w0 = wsm[tx * 2][j],     w1 = wsm[tx * 2 + 1][j];
            acc[0][0] += a0 * w0;  acc[0][1] += a0 * w1;
            acc[1][0] += a1 * w0;  acc[1][1] += a1 * w1;
        }
    }
#pragma unroll
    for (int p = 0; p < 2; p++)
#pragma unroll
        for (int q = 0; q < 2; q++) {
            int o = o0 + tx * 2 + q;
            out[(size_t)(b0 + ty * 2 + p) * OUT_DIM + o] = acc[p][q] + bb[o] + dbb[o];
        }
}

// ---------------- k_main: z-stationary fp16 mma, distance-2 pipeline, LDS.128 layout ----------------
// Tile word layout, per row r (= o'*8 + i'):  word[ j*16 + tig*4 + {0,1,2,3} ]
//   = { b0(kb=2j,tig), b1(kb=2j,tig), b0(kb=2j+1,tig), b1(kb=2j+1,tig) }
// where b0(kb,tig) = halves k = kb*16 + 2*tig, +1 ; b1 = halves k = kb*16 + 2*tig+8, +9.
// Row stride 80 words (== 16 mod 32): LDS.128 bank base = 16*g + 4*tig -> conflict-free.
__global__ void __launch_bounds__(256, 2)
k_main(const float* __restrict__ x, const float* __restrict__ z,
       const float* __restrict__ dwW, float* __restrict__ out) {
    __shared__ __align__(16) uint32_t ws[2][NO_ * 8][ROWW];

    const int tid  = threadIdx.x;
    const int w    = tid >> 5;
    const int lane = tid & 31;
    const int g    = lane >> 2;   // groupID
    const int tig  = lane & 3;    // threadID in group
    const int o0   = blockIdx.x * NO_;
    const int ibase = blockIdx.y * I_PER;
    const int b0r = w * 16 + g;
    const int b1r = b0r + 8;

    // --- z A-fragments (m16n8k16): loop-invariant, register-resident fp16 ---
    uint32_t zA[8][4];
    {
        const float* z0 = z + (size_t)b0r * ZD;
        const float* z1 = z + (size_t)b1r * ZD;
#pragma unroll
        for (int kb = 0; kb < 8; kb++) {
            int c = kb * 16 + 2 * tig;
            zA[kb][0] = f2h2(z0[c],     z0[c + 1]);
            zA[kb][1] = f2h2(z1[c],     z1[c + 1]);
            zA[kb][2] = f2h2(z0[c + 8], z0[c + 9]);
            zA[kb][3] = f2h2(z1[c + 8], z1[c + 9]);
        }
    }

    // --- staging: thread owns (row sr, kb = sc): 16 consecutive floats ---
    const int sr = tid >> 3;            // 0..31
    const int sc = tid & 7;             // 0..7 (= kb)
    const int j0 = sc >> 1;             // kb pair
    const int e0 = sc & 1;              // kb parity
    const float4* tsrc = (const float4*)(dwW
        + ((size_t)(o0 + (sr >> 3)) * IN_DIM + ibase + (sr & 7)) * ZD + sc * 16);
    uint32_t* sdst = &ws[0][0][0] + sr * ROWW + j0 * 16 + e0 * 2;

    float4 pre[4];

    // pack+store of pre[] (16 floats of kb=sc) into buffer bsel, LDS.128 layout
#define STS_TILE(bsel)                                                              \
    do {                                                                            \
        uint32_t* d = sdst + (bsel) * (NO_ * 8 * ROWW);                             \
        *(uint2*)(d + 0)  = make_uint2(f2h2(pre[0].x, pre[0].y),                    \
                                       f2h2(pre[2].x, pre[2].y));                   \
        *(uint2*)(d + 4)  = make_uint2(f2h2(pre[0].z, pre[0].w),                    \
                                       f2h2(pre[2].z, pre[2].w));                   \
        *(uint2*)(d + 8)  = make_uint2(f2h2(pre[1].x, pre[1].y),                    \
                                       f2h2(pre[3].x, pre[3].y));                   \
        *(uint2*)(d + 12) = make_uint2(f2h2(pre[1].z, pre[1].w),                    \
                                       f2h2(pre[3].z, pre[3].w));                   \
    } while (0)

    // prologue: T0 -> buf0, T1 -> pre
#pragma unroll
    for (int q = 0; q < 4; q++) pre[q] = __ldg(tsrc + q);
    STS_TILE(0);
#pragma unroll
    for (int q = 0; q < 4; q++) pre[q] = __ldg(tsrc + 256 + q);
    __syncthreads();

    float pout[NO_][2];
#pragma unroll
    for (int o = 0; o < NO_; o++) { pout[o][0] = 0.f; pout[o][1] = 0.f; }

    const float* xp0 = x + (size_t)b0r * IN_DIM + ibase + 2 * tig;
    const float* xp1 = x + (size_t)b1r * IN_DIM + ibase + 2 * tig;

#pragma unroll 1
    for (int it = 0; it < ITERS; ++it) {
        // 1) stage T_{it+1} from pre
        if (it + 1 < ITERS) STS_TILE((it + 1) & 1);
        // 2) prefetch T_{it+2}
        if (it + 2 < ITERS) {
            const float4* p = tsrc + (size_t)(it + 2) * 256;
#pragma unroll
            for (int q = 0; q < 4; q++) pre[q] = __ldg(p + q);
        }

        // 3) compute T_it: 16 conflict-free LDS.128, 32 MMAs
        const uint32_t* rb = &ws[it & 1][0][0];
        float c[NO_][4];
#pragma unroll
        for (int o = 0; o < NO_; o++)
            c[o][0] = c[o][1] = c[o][2] = c[o][3] = 0.f;
#pragma unroll
        for (int j = 0; j < 4; j++) {
#pragma unroll
            for (int o = 0; o < NO_; o++) {
                uint4 v = *(const uint4*)(rb + (o * 8 + g) * ROWW + j * 16 + tig * 4);
                mma_fp16(c[o], zA[2 * j],     v.x, v.y);
                mma_fp16(c[o], zA[2 * j + 1], v.z, v.w);
            }
        }

        // 4) epilogue: contract 8 i-columns against x (fp32)
        float2 xa = *(const float2*)(xp0 + it * 8);
        float2 xb = *(const float2*)(xp1 + it * 8);
#pragma unroll
        for (int o = 0; o < NO_; o++) {
            pout[o][0] += c[o][0] * xa.x + c[o][1] * xa.y;
            pout[o][1] += c[o][2] * xb.x + c[o][3] * xb.y;
        }

        // 5) single barrier per iter
        __syncthreads();
    }
#undef STS_TILE

    // --- reduce over tig and accumulate ---
#pragma unroll
    for (int o = 0; o < NO_; o++) {
        float v0 = pout[o][0];
        float v1 = pout[o][1];
        v0 += __shfl_xor_sync(0xffffffffu, v0, 1);
        v0 += __shfl_xor_sync(0xffffffffu, v0, 2);
        v1 += __shfl_xor_sync(0xffffffffu, v1, 1);
        v1 += __shfl_xor_sync(0xffffffffu, v1, 2);
        if (tig == 0) {
            atomicAdd(&out[(size_t)b0r * OUT_DIM + o0 + o], v0);
            atomicAdd(&out[(size_t)b1r * OUT_DIM + o0 + o], v1);
        }
    }
}

// ---------------- launch ----------------
extern "C" void kernel_launch(void* const* d_in, const int* in_sizes, int n_in,
                              void* d_out, int out_size) {
    const float* x   = (const float*)d_in[0];
    const float* z   = (const float*)d_in[1];
    const float* bw  = (const float*)d_in[2];
    const float* dwW = (const float*)d_in[3];
    const float* dwb = (const float*)d_in[4];
    const float* bb  = (const float*)d_in[5];
    const float* dbW = (const float*)d_in[6];
    const float* dbb = (const float*)d_in[7];
    float* out = (float*)d_out;

    k_pre<<<dim3(OUT_DIM / 32, BATCH / 32), 256>>>(x, z, bw, dwb, bb, dbW, dbb, out);
    k_main<<<dim3(OUT_DIM / NO_, ISPLIT), 256>>>(x, z, dwW, out);
}

// round 15
// speedup vs baseline: 1.2739x; 1.2739x over previous
#include <cuda_runtime.h>
#include <cuda_fp16.h>
#include <cstdint>

#define BATCH   128
#define IN_DIM  1024
#define OUT_DIM 1024
#define ZD      128

#define ISPLIT  4                    // i-range splits
#define I_PER   (IN_DIM / ISPLIT)    // 256
#define NIT     2                    // i-columns per iter
#define ITERS   (I_PER / NIT)        // 128
#define RS      144                  // tile row stride (words): 16 mod 32 -> LDS.128 conflict-free
#define TILEW   (16 * RS)            // words per buffer

__device__ float g_xT[IN_DIM * BATCH];   // xT[i*128 + b]

// ---------------- helpers ----------------
__device__ __forceinline__ void mma_fp16(float* c, const uint32_t* a,
                                         uint32_t b0, uint32_t b1) {
    asm volatile(
        "mma.sync.aligned.m16n8k16.row.col.f32.f16.f16.f32 "
        "{%0,%1,%2,%3},{%4,%5,%6,%7},{%8,%9},{%0,%1,%2,%3};"
        : "+f"(c[0]), "+f"(c[1]), "+f"(c[2]), "+f"(c[3])
        : "r"(a[0]), "r"(a[1]), "r"(a[2]), "r"(a[3]), "r"(b0), "r"(b1));
}
__device__ __forceinline__ uint32_t f2h2(float lo, float hi) {
    __half2 h = __float22half2_rn(make_float2(lo, hi));
    return *(uint32_t*)&h;
}
__device__ __forceinline__ uint32_t hmul2u(uint32_t a, uint32_t b) {
    __half2 r = __hmul2(*(__half2*)&a, *(__half2*)&b);
    return *(uint32_t*)&r;
}

// ---------------- k_prep: transpose x -> g_xT ----------------
__global__ void k_prep(const float* __restrict__ x) {
    __shared__ float tile[32][33];
    int rb = blockIdx.x >> 5;    // 0..3  batch block
    int cb = blockIdx.x & 31;    // 0..31 i block
    int tx = threadIdx.x, ty = threadIdx.y;  // 32 x 8
#pragma unroll
    for (int k = 0; k < 4; k++)
        tile[ty + 8 * k][tx] = x[(size_t)(rb * 32 + ty + 8 * k) * IN_DIM + cb * 32 + tx];
    __syncthreads();
#pragma unroll
    for (int k = 0; k < 4; k++)
        g_xT[(size_t)(cb * 32 + ty + 8 * k) * BATCH + rb * 32 + tx] = tile[tx][ty + 8 * k];
}

// ---------------- k_pre: out = bb + dbb + z@dbW^T + x@(bw+dwb)^T (overwrite) ----------------
__global__ void __launch_bounds__(256)
k_pre(const float* __restrict__ x, const float* __restrict__ z,
      const float* __restrict__ bw, const float* __restrict__ dwb,
      const float* __restrict__ bb, const float* __restrict__ dbW,
      const float* __restrict__ dbb, float* __restrict__ out) {
    __shared__ float as_[16][36];
    __shared__ float wsm[32][36];
    const int t  = threadIdx.x;
    const int o0 = blockIdx.x * 32;
    const int b0 = blockIdx.y * 16;
    const int ty = t >> 4;   // 0..15 batch row
    const int tx = t & 15;   // o cols tx, tx+16
    const int lr = t >> 3;   // 0..31
    const int lc = (t & 7) * 4;
    float acc0 = 0.f, acc1 = 0.f;
    for (int kt = 0; kt < 36; kt++) {
        float4 av, wv;
        if (t < 128) {
            if (kt < 4) av = *(const float4*)(z + (size_t)(b0 + lr) * ZD + kt * 32 + lc);
            else        av = *(const float4*)(x + (size_t)(b0 + lr) * IN_DIM + (kt - 4) * 32 + lc);
        }
        if (kt < 4) {
            wv = *(const float4*)(dbW + (size_t)(o0 + lr) * ZD + kt * 32 + lc);
        } else {
            size_t off = (size_t)(o0 + lr) * IN_DIM + (kt - 4) * 32 + lc;
            float4 a = *(const float4*)(bw + off);
            float4 d = *(const float4*)(dwb + off);
            wv = make_float4(a.x + d.x, a.y + d.y, a.z + d.z, a.w + d.w);
        }
        __syncthreads();
        if (t < 128) *(float4*)&as_[lr & 15][lc] = av;
        *(float4*)&wsm[lr][lc] = wv;
        __syncthreads();
#pragma unroll 8
        for (int j = 0; j < 32; j++) {
            float a = as_[ty][j];
            acc0 += a * wsm[tx][j];
            acc1 += a * wsm[tx + 16][j];
        }
    }
    {
        int o = o0 + tx;
        out[(size_t)(b0 + ty) * OUT_DIM + o]      = acc0 + bb[o] + dbb[o];
        out[(size_t)(b0 + ty) * OUT_DIM + o + 16] = acc1 + bb[o + 16] + dbb[o + 16];
    }
}

// ---------------- k_main: M-operand fp16 MMA  C[b,o] += (x*z) @ W^T ----------------
// Tile (per iter): W rows o0..o0+16, i-cols {it*2, it*2+1}, all 128 k.
// Row layout (RS=144 words): word[i'*64 + j*16 + tig*4 + {0,1,2,3}] =
//   { b0(kb=2j), b1(kb=2j), b0(kb=2j+1), b1(2j+1) } for this tig.
__global__ void __launch_bounds__(256, 2)
k_main(const float* __restrict__ z, const float* __restrict__ dwW,
       float* __restrict__ out) {
    __shared__ __align__(16) uint32_t ws[2][TILEW];

    const int tid  = threadIdx.x;
    const int w    = tid >> 5;
    const int lane = tid & 31;
    const int g    = lane >> 2;
    const int tig  = lane & 3;
    const int ih   = w >> 2;     // i-half of each iter (which of the 2 i-cols)
    const int bq   = w & 3;      // batch quarter (32 rows via 2 m-blocks)
    const int o0   = blockIdx.x * 16;
    const int ibase = blockIdx.y * I_PER;

    // --- z A-fragments for 32 batch rows (2 m-blocks), register-resident ---
    uint32_t zA[2][8][4];
#pragma unroll
    for (int mb = 0; mb < 2; mb++) {
        const float* z0 = z + (size_t)(bq * 32 + mb * 16 + g) * ZD;
        const float* z1 = z0 + 8 * ZD;
#pragma unroll
        for (int kb = 0; kb < 8; kb++) {
            int c = kb * 16 + 2 * tig;
            zA[mb][kb][0] = f2h2(z0[c],     z0[c + 1]);
            zA[mb][kb][1] = f2h2(z1[c],     z1[c + 1]);
            zA[mb][kb][2] = f2h2(z0[c + 8], z0[c + 9]);
            zA[mb][kb][3] = f2h2(z1[c + 8], z1[c + 9]);
        }
    }

    // --- staging: q-th task = run (o' = q*4 + w/2, i' = w&1), lane = 16B chunk ---
    // gmem: perfectly coalesced 512B per warp-LDG.
    const int op0 = w >> 1;          // o' for q=0
    const int ip  = w & 1;           // i'
    const float4* tsrc = (const float4*)(dwW
        + ((size_t)(o0 + op0) * IN_DIM + ibase + ip) * ZD) + lane;
    // q stride: 4 o-rows = 4*IN_DIM*ZD floats = 131072 float4 ; iter stride: NIT*ZD = 64 float4
    const int kb_ = lane >> 2, pos4 = lane & 3;
    const int coff = (kb_ >> 1) * 16 + (kb_ & 1) * 2 + (pos4 & 1) * 8 + (pos4 >> 1);
    const int sb0 = op0 * RS + ip * 64 + coff;   // word offset for q=0 (+ q*4*RS per q)

    float4 pre[4];
#define LDG_TILE(itv)                                                          \
    do {                                                                       \
        const float4* p = tsrc + (size_t)(itv) * 64;                           \
        pre[0] = __ldg(p);                                                     \
        pre[1] = __ldg(p + 131072);                                            \
        pre[2] = __ldg(p + 262144);                                            \
        pre[3] = __ldg(p + 393216);                                            \
    } while (0)
#define STS_TILE(bsel)                                                         \
    do {                                                                       \
        uint32_t* d = &ws[bsel][sb0];                                          \
        d[0]            = f2h2(pre[0].x, pre[0].y);                            \
        d[4]            = f2h2(pre[0].z, pre[0].w);                            \
        d[4 * RS]       = f2h2(pre[1].x, pre[1].y);                            \
        d[4 * RS + 4]   = f2h2(pre[1].z, pre[1].w);                            \
        d[8 * RS]       = f2h2(pre[2].x, pre[2].y);                            \
        d[8 * RS + 4]   = f2h2(pre[2].z, pre[2].w);                            \
        d[12 * RS]      = f2h2(pre[3].x, pre[3].y);                            \
        d[12 * RS + 4]  = f2h2(pre[3].z, pre[3].w);                            \
    } while (0)

    // prologue: T0 -> buf0, T1 -> pre
    LDG_TILE(0);
    STS_TILE(0);
    LDG_TILE(1);
    __syncthreads();

    float c[2][2][4] = {};   // [nb][mb][4]

#pragma unroll 1
    for (int it = 0; it < ITERS; ++it) {
        // x values for this iter's i-column (broadcast loads from transposed x)
        const float* xcol = g_xT + (size_t)(ibase + it * NIT + ih) * BATCH + bq * 32 + g;
        uint32_t xh[2][2];
#pragma unroll
        for (int mb = 0; mb < 2; mb++) {
            float x0 = __ldg(xcol + mb * 16);
            float x1 = __ldg(xcol + mb * 16 + 8);
            xh[mb][0] = f2h2(x0, x0);
            xh[mb][1] = f2h2(x1, x1);
        }

        // stage T_{it+1}; prefetch T_{it+2}
        if (it + 1 < ITERS) STS_TILE((it + 1) & 1);
        if (it + 2 < ITERS) LDG_TILE(it + 2);

        // compute T_it
        const uint32_t* rb_ = &ws[it & 1][0];
#pragma unroll
        for (int j = 0; j < 4; j++) {
            uint4 v0 = *(const uint4*)(rb_ + g * RS + ih * 64 + j * 16 + tig * 4);
            uint4 v1 = *(const uint4*)(rb_ + (8 + g) * RS + ih * 64 + j * 16 + tig * 4);
#pragma unroll
            for (int e = 0; e < 2; e++) {
                const int kb = 2 * j + e;
                const uint32_t b00 = e ? v0.z : v0.x, b01 = e ? v0.w : v0.y;
                const uint32_t b10 = e ? v1.z : v1.x, b11 = e ? v1.w : v1.y;
#pragma unroll
                for (int mb = 0; mb < 2; mb++) {
                    uint32_t sa[4];
                    sa[0] = hmul2u(zA[mb][kb][0], xh[mb][0]);
                    sa[1] = hmul2u(zA[mb][kb][1], xh[mb][1]);
                    sa[2] = hmul2u(zA[mb][kb][2], xh[mb][0]);
                    sa[3] = hmul2u(zA[mb][kb][3], xh[mb][1]);
                    mma_fp16(c[0][mb], sa, b00, b01);
                    mma_fp16(c[1][mb], sa, b10, b11);
                }
            }
        }
        __syncthreads();
    }
#undef STS_TILE
#undef LDG_TILE

    // --- final: direct accumulate (8 contenders per cell: 4 isplit x 2 ih) ---
#pragma unroll
    for (int nb = 0; nb < 2; nb++)
#pragma unroll
        for (int mb = 0; mb < 2; mb++) {
            const float* cc = c[nb][mb];
            int ob = o0 + nb * 8 + 2 * tig;
            int br = bq * 32 + mb * 16 + g;
            atomicAdd(&out[(size_t)br * OUT_DIM + ob],           cc[0]);
            atomicAdd(&out[(size_t)br * OUT_DIM + ob + 1],       cc[1]);
            atomicAdd(&out[(size_t)(br + 8) * OUT_DIM + ob],     cc[2]);
            atomicAdd(&out[(size_t)(br + 8) * OUT_DIM + ob + 1], cc[3]);
        }
}

// ---------------- launch ----------------
extern "C" void kernel_launch(void* const* d_in, const int* in_sizes, int n_in,
                              void* d_out, int out_size) {
    const float* x   = (const float*)d_in[0];
    const float* z   = (const float*)d_in[1];
    const float* bw  = (const float*)d_in[2];
    const float* dwW = (const float*)d_in[3];
    const float* dwb = (const float*)d_in[4];
    const float* bb  = (const float*)d_in[5];
    const float* dbW = (const float*)d_in[6];
    const float* dbb = (const float*)d_in[7];
    float* out = (float*)d_out;

    k_prep<<<128, dim3(32, 8)>>>(x);
    k_pre<<<dim3(OUT_DIM / 32, BATCH / 16), 256>>>(x, z, bw, dwb, bb, dbW, dbb, out);
    k_main<<<dim3(OUT_DIM / 16, ISPLIT), 256>>>(z, dwW, out);
}